// round 12
// baseline (speedup 1.0000x reference)
#include <cuda_runtime.h>
#include <cstdint>
#include <cstddef>

// ---------------- Problem constants ----------------
#define BTOT 16384   // b*n
#define FIN  2048
#define CIN  128
#define CFF  512
#define COUT 128
#define TPOS 16
#define BM   128
#define CH   64
#define NCHUNK 8
#define NTH  512

// ---------------- SMEM float offsets (XOR-swizzled, no padding) ----------------
// sA   [k=128][r=128]          @ 0       (16384 fl)
// sW1  [2][k=128][n=64]        @ 16384   (2 x 8192)
// sH   [2][k=64][r=128]        @ 32768   (2 x 8192)   <-- double-buffered
// sW2  [k=64][o=128]           @ 49152   (8192)
#define SA_OFF   0
#define SW1_OFF  16384
#define SH_OFF   32768
#define SW2_OFF  49152
#define SMEM_FLOATS 57344
#define SMEM_BYTES (SMEM_FLOATS * 4)   // 229376 B (<= 232448 cap)
#define OS 132                          // epilogue sOut [o][r] stride (overlay @0)

// Named barriers: per-buffer produced/consumed pairs (race-free pairing)
#define BAR_P0 1   // sH[0] produced (G1 arrive, G2 sync)
#define BAR_P1 2   // sH[1] produced
#define BAR_C0 3   // sH[0] consumed (G2 arrive, G1 sync)
#define BAR_C1 4   // sH[1] consumed
#define BAR_G1 5   // G1-internal (256)
#define BAR_G2 6   // G2-internal (256)

#define BARN(id, cnt)  asm volatile("bar.sync %0, %1;"   :: "r"(id), "r"(cnt) : "memory")
#define BARA(id, cnt)  asm volatile("bar.arrive %0, %1;" :: "r"(id), "r"(cnt) : "memory")

#define CP_ASYNC16(saddr, gptr) \
    asm volatile("cp.async.cg.shared.global [%0], [%1], 16;" :: "r"(saddr), "l"(gptr) : "memory")
#define CP_COMMIT() asm volatile("cp.async.commit_group;" ::: "memory")
#define CP_WAIT(n)  asm volatile("cp.async.wait_group %0;" :: "n"(n) : "memory")

// ---------------- Scratch (allocation-free rule) ----------------
__device__ float g_xT [2048ull * 16384];   // xT[f][row], f = c*16+t  (tf32-rounded)
__device__ float g_yT [2048ull * 16384];   // yT[f][row], f = o*16+t
__device__ float g_w1t[2048 * 512];        // w1t[(c*16+t)][o]        (tf32-rounded)
__device__ float g_w2t[8192 * 128];        // w2t[(k*16+t)][o]        (tf32-rounded)

__device__ __forceinline__ uint32_t smem_u32(const void* p) {
    uint32_t a;
    asm("{ .reg .u64 t; cvta.to.shared.u64 t, %1; cvt.u32.u64 %0, t; }" : "=r"(a) : "l"(p));
    return a;
}
__device__ __forceinline__ float tf32r(float x) {
    unsigned r;
    asm("cvt.rna.tf32.f32 %0, %1;" : "=r"(r) : "f"(x));
    return __uint_as_float(r);
}
__device__ __forceinline__ float gelu_exact(float v) {
    return 0.5f * v * (1.0f + erff(v * 0.70710678118654752440f));
}
__device__ __forceinline__ void mma_tf32(float c[4], const unsigned a[4],
                                         unsigned b0, unsigned b1) {
    asm volatile(
        "mma.sync.aligned.m16n8k8.row.col.f32.tf32.tf32.f32 "
        "{%0,%1,%2,%3}, {%4,%5,%6,%7}, {%8,%9}, {%0,%1,%2,%3};\n"
        : "+f"(c[0]), "+f"(c[1]), "+f"(c[2]), "+f"(c[3])
        : "r"(a[0]), "r"(a[1]), "r"(a[2]), "r"(a[3]), "r"(b0), "r"(b1));
}

// ------------- Tiled transpose (+ optional tf32-RNA rounding): out[C][R] = in^T -------------
__global__ void transpose_kernel(float* __restrict__ out, const float* __restrict__ in,
                                 int R, int C, int doRound) {
    __shared__ float tile[32][33];
    const int bx = blockIdx.x * 32, by = blockIdx.y * 32;
    const int x = threadIdx.x & 31, y0 = threadIdx.x >> 5;
#pragma unroll
    for (int j = 0; j < 32; j += 8) {
        const int r = by + y0 + j, c = bx + x;
        if (r < R && c < C) {
            float v = in[(size_t)r * C + c];
            tile[y0 + j][x] = doRound ? tf32r(v) : v;
        }
    }
    __syncthreads();
#pragma unroll
    for (int j = 0; j < 32; j += 8) {
        const int c = bx + y0 + j, r = by + x;
        if (c < C && r < R) out[(size_t)c * R + r] = tile[x][y0 + j];
    }
}

// ------------------------------- Main warp-specialized kernel ----------------------------
__global__ void __launch_bounds__(NTH, 1)
jff_ws_kernel(const float* __restrict__ xT,
              const float* __restrict__ w1t,
              const float* __restrict__ w2t,
              float* __restrict__ yT)
{
    extern __shared__ float smem[];
    float* sA  = smem + SA_OFF;
    float* sW1 = smem + SW1_OFF;     // 2 buffers of 8192
    float* sH  = smem + SH_OFF;      // 2 buffers of 8192
    float* sW2 = smem + SW2_OFF;
    const uint32_t sb = smem_u32(smem);

    const int t   = blockIdx.x;      // t fastest -> L2 reuse of xT across t
    const int m0  = blockIdx.y * BM;
    const int tid = threadIdx.x;
    const int lane = tid & 31;
    const int g  = lane >> 2;        // 0..7
    const int qp = lane & 3;         // 0..3
    const int sw = qp << 3;          // XOR-swizzle term (thread-constant)

    if (tid < 256) {
        // ================= G1: GEMM1 + GELU producer =================
        const int w  = tid >> 5;         // 0..7
        const int wm = w & 3;            // 32-row slice
        const int wn = w >> 2;           // 0..1: 32-n slice

        // -- stage A tile via cp.async: 4096 16B chunks, 16 per thread --
#pragma unroll
        for (int i = 0; i < 16; i++) {
            const int q = tid + 256 * i;
            const int k = q >> 5, rq = q & 31;
            const uint32_t dst = sb + (uint32_t)(SA_OFF + k * 128 + ((4 * rq) ^ ((k & 3) << 3))) * 4;
            CP_ASYNC16(dst, &xT[(size_t)(k * TPOS + t) * BTOT + m0 + 4 * rq]);
        }
        CP_COMMIT();                                        // group: A
        // -- pre-stage W1 chunk 0 and 1 --
#pragma unroll
        for (int b = 0; b < 2; b++) {
#pragma unroll
            for (int i = 0; i < 8; i++) {
                const int q = tid + 256 * i;
                const int k = q >> 4, nq = q & 15;
                const uint32_t dst = sb + (uint32_t)(SW1_OFF + b * 8192 + k * 64 +
                                                     ((4 * nq) ^ ((k & 3) << 3))) * 4;
                CP_ASYNC16(dst, &w1t[(size_t)(k * TPOS + t) * CFF + b * CH + 4 * nq]);
            }
            CP_COMMIT();                                    // groups: W1[0], W1[1]
        }

        // thread-constant swizzled row indices
        int ra[2][2], rb[4];
#pragma unroll
        for (int mi = 0; mi < 2; mi++)
#pragma unroll
            for (int h = 0; h < 2; h++)
                ra[mi][h] = (wm * 32 + mi * 16 + h * 8 + g) ^ sw;
#pragma unroll
        for (int ni = 0; ni < 4; ni++)
            rb[ni] = (wn * 32 + ni * 8 + g) ^ sw;
        const int swHe = ((2 * qp) & 3) << 3;
        const int swHo = ((2 * qp + 1) & 3) << 3;

#pragma unroll 1
        for (int ch = 0; ch < NCHUNK; ch++) {
            if (ch < 7) { CP_WAIT(1); } else { CP_WAIT(0); }
            BARN(BAR_G1, 256);                              // W1[ch&1] (and A) visible group-wide
            const float* W1b = sW1 + (ch & 1) * 8192;

            // ---- GEMM1: c1[32r x 32n] = A[.,128] * W1^T ----
            float c1[2][4][4];
#pragma unroll
            for (int mi = 0; mi < 2; mi++)
#pragma unroll
                for (int ni = 0; ni < 4; ni++)
#pragma unroll
                    for (int j = 0; j < 4; j++) c1[mi][ni][j] = 0.0f;

#pragma unroll
            for (int ks = 0; ks < 16; ks++) {
                const int kA = ks * 8 + qp;
                unsigned a[2][4];
#pragma unroll
                for (int mi = 0; mi < 2; mi++) {
                    a[mi][0] = __float_as_uint(sA[kA * 128 + ra[mi][0]]);
                    a[mi][1] = __float_as_uint(sA[kA * 128 + ra[mi][1]]);
                    a[mi][2] = __float_as_uint(sA[(kA + 4) * 128 + ra[mi][0]]);
                    a[mi][3] = __float_as_uint(sA[(kA + 4) * 128 + ra[mi][1]]);
                }
#pragma unroll
                for (int ni = 0; ni < 4; ni++) {
                    const unsigned b0 = __float_as_uint(W1b[kA * 64 + rb[ni]]);
                    const unsigned b1 = __float_as_uint(W1b[(kA + 4) * 64 + rb[ni]]);
#pragma unroll
                    for (int mi = 0; mi < 2; mi++) mma_tf32(c1[mi][ni], a[mi], b0, b1);
                }
            }
            BARN(BAR_G1, 256);                              // all G1 done reading W1[ch&1]
            if (ch < 6) {                                   // restage this buffer for ch+2
#pragma unroll
                for (int i = 0; i < 8; i++) {
                    const int q = tid + 256 * i;
                    const int k = q >> 4, nq = q & 15;
                    const uint32_t dst = sb + (uint32_t)(SW1_OFF + (ch & 1) * 8192 + k * 64 +
                                                         ((4 * nq) ^ ((k & 3) << 3))) * 4;
                    CP_ASYNC16(dst, &w1t[(size_t)(k * TPOS + t) * CFF + (ch + 2) * CH + 4 * nq]);
                }
                CP_COMMIT();
            }

            if (ch >= 2) BARN(BAR_C0 + (ch & 1), 512);      // G2 done with sH[ch&1] (chunk ch-2)

            // ---- exact GELU -> tf32 -> sH[ch&1][n][r] ----
            float* sHb = sH + (ch & 1) * 8192;
#pragma unroll
            for (int mi = 0; mi < 2; mi++) {
                const int r0 = wm * 32 + mi * 16 + g;
#pragma unroll
                for (int ni = 0; ni < 4; ni++) {
                    const int ne = wn * 32 + ni * 8 + 2 * qp;
                    sHb[ne * 128 + (r0 ^ swHe)]             = tf32r(gelu_exact(c1[mi][ni][0]));
                    sHb[(ne + 1) * 128 + (r0 ^ swHo)]       = tf32r(gelu_exact(c1[mi][ni][1]));
                    sHb[ne * 128 + ((r0 + 8) ^ swHe)]       = tf32r(gelu_exact(c1[mi][ni][2]));
                    sHb[(ne + 1) * 128 + ((r0 + 8) ^ swHo)] = tf32r(gelu_exact(c1[mi][ni][3]));
                }
            }
            BARA(BAR_P0 + (ch & 1), 512);                   // publish sH[ch&1] (chunk ch)
        }
        // drain G2's final consumption arrivals (ch=6 on C0, ch=7 on C1)
        BARN(BAR_C0, 512);
        BARN(BAR_C1, 512);
    } else {
        // ================= G2: GEMM2 consumer =================
        const int u  = tid - 256;
        const int w  = u >> 5;           // 0..7
        const int wm = w & 3;            // 32-row slice
        const int wn = w >> 2;           // 0..1: 64-o slice

        // -- pre-stage W2 chunk 0 --
#pragma unroll
        for (int i = 0; i < 8; i++) {
            const int q = u + 256 * i;
            const int k = q >> 5, oq = q & 31;
            const uint32_t dst = sb + (uint32_t)(SW2_OFF + k * 128 + ((4 * oq) ^ ((k & 3) << 3))) * 4;
            CP_ASYNC16(dst, &w2t[(size_t)(k * TPOS + t) * COUT + 4 * oq]);
        }
        CP_COMMIT();

        int rh[2][2], ro[8];
#pragma unroll
        for (int mi = 0; mi < 2; mi++)
#pragma unroll
            for (int h = 0; h < 2; h++)
                rh[mi][h] = (wm * 32 + mi * 16 + h * 8 + g) ^ sw;
#pragma unroll
        for (int ni = 0; ni < 8; ni++)
            ro[ni] = (wn * 64 + ni * 8 + g) ^ sw;

        float acc[2][8][4];
#pragma unroll
        for (int mi = 0; mi < 2; mi++)
#pragma unroll
            for (int ni = 0; ni < 8; ni++)
#pragma unroll
                for (int j = 0; j < 4; j++) acc[mi][ni][j] = 0.0f;

#pragma unroll 1
        for (int ch = 0; ch < NCHUNK; ch++) {
            CP_WAIT(0);
            BARN(BAR_G2, 256);                              // W2(ch) visible group-wide
            BARN(BAR_P0 + (ch & 1), 512);                   // sH[ch&1] produced (chunk ch)
            const float* sHb = sH + (ch & 1) * 8192;

            // ---- GEMM2: acc[32r x 64o] += H * W2^T ----
#pragma unroll
            for (int ks = 0; ks < 8; ks++) {
                const int kA = ks * 8 + qp;
                unsigned a[2][4];
#pragma unroll
                for (int mi = 0; mi < 2; mi++) {
                    a[mi][0] = __float_as_uint(sHb[kA * 128 + rh[mi][0]]);
                    a[mi][1] = __float_as_uint(sHb[kA * 128 + rh[mi][1]]);
                    a[mi][2] = __float_as_uint(sHb[(kA + 4) * 128 + rh[mi][0]]);
                    a[mi][3] = __float_as_uint(sHb[(kA + 4) * 128 + rh[mi][1]]);
                }
#pragma unroll
                for (int ni = 0; ni < 8; ni++) {
                    const unsigned b0 = __float_as_uint(sW2[kA * 128 + ro[ni]]);
                    const unsigned b1 = __float_as_uint(sW2[(kA + 4) * 128 + ro[ni]]);
#pragma unroll
                    for (int mi = 0; mi < 2; mi++) mma_tf32(acc[mi][ni], a[mi], b0, b1);
                }
            }
            BARN(BAR_G2, 256);                              // all G2 done reading W2(ch)
            if (ch < 7) {                                   // restage W2 for ch+1
#pragma unroll
                for (int i = 0; i < 8; i++) {
                    const int q = u + 256 * i;
                    const int k = q >> 5, oq = q & 31;
                    const uint32_t dst = sb + (uint32_t)(SW2_OFF + k * 128 +
                                                         ((4 * oq) ^ ((k & 3) << 3))) * 4;
                    CP_ASYNC16(dst, &w2t[(size_t)((ch + 1) * CH * TPOS + k * TPOS + t) * COUT + 4 * oq]);
                }
                CP_COMMIT();
            }
            BARA(BAR_C0 + (ch & 1), 512);                   // sH[ch&1] consumed
        }

        // ---- G2 writes acc -> sO[o][r] (overlay @0, conflict-free: banks 8qp+g) ----
        // Safe: G1's last sA read (GEMM1 ch7) happens-before P1(ch7) arrive,
        // which happens-before this point (we synced P1 at ch7).
        float* sO = smem;
#pragma unroll
        for (int mi = 0; mi < 2; mi++) {
            const int r0 = wm * 32 + mi * 16 + g;
#pragma unroll
            for (int ni = 0; ni < 8; ni++) {
                const int o0 = wn * 64 + ni * 8 + 2 * qp;
                sO[o0 * OS + r0]           = acc[mi][ni][0];
                sO[(o0 + 1) * OS + r0]     = acc[mi][ni][1];
                sO[o0 * OS + r0 + 8]       = acc[mi][ni][2];
                sO[(o0 + 1) * OS + r0 + 8] = acc[mi][ni][3];
            }
        }
    }

    __syncthreads();
    // ---- all 512 threads: coalesced yT stores ----
    {
        float* sO = smem;
#pragma unroll
        for (int i = 0; i < 8; i++) {
            const int idx = tid + NTH * i;                  // 4096 float4 slots
            const int o = idx >> 5, rq = idx & 31;
            const float4 v = *(const float4*)&sO[o * OS + 4 * rq];
            *(float4*)&yT[(size_t)(o * TPOS + t) * BTOT + m0 + 4 * rq] = v;
        }
    }
}

extern "C" void kernel_launch(void* const* d_in, const int* in_sizes, int n_in,
                              void* d_out, int out_size)
{
    const float* x  = (const float*)d_in[0];   // [16384, 2048] fp32
    const float* w1 = (const float*)d_in[1];   // [512,128,16]  fp32
    const float* w2 = (const float*)d_in[2];   // [128,512,16]  fp32
    float* y = (float*)d_out;                  // [16384, 2048] fp32
    (void)in_sizes; (void)n_in; (void)out_size;

    float *xT, *yT, *w1t, *w2t;
    cudaGetSymbolAddress((void**)&xT,  g_xT);
    cudaGetSymbolAddress((void**)&yT,  g_yT);
    cudaGetSymbolAddress((void**)&w1t, g_w1t);
    cudaGetSymbolAddress((void**)&w2t, g_w2t);

    cudaFuncSetAttribute(jff_ws_kernel,
                         cudaFuncAttributeMaxDynamicSharedMemorySize, SMEM_BYTES);

    // 1) Layout transforms with tf32-RNA rounding folded in (raw-byte cp.async later)
    transpose_kernel<<<dim3(FIN / 32, BTOT / 32), 256>>>(xT, x, BTOT, FIN, 1);
    transpose_kernel<<<dim3(2048 / 32, 512 / 32), 256>>>(w1t, w1, CFF, CIN * TPOS, 1);
    transpose_kernel<<<dim3(8192 / 32, 128 / 32), 256>>>(w2t, w2, COUT, CFF * TPOS, 1);

    // 2) Warp-specialized fused locally-connected FFN (writes yT[f][row])
    dim3 grid(TPOS, BTOT / BM);
    jff_ws_kernel<<<grid, NTH, SMEM_BYTES>>>(xT, w1t, w2t, yT);

    // 3) yT -> y (no rounding)
    transpose_kernel<<<dim3(BTOT / 32, FIN / 32), 256>>>(y, yT, FIN, BTOT, 0);
}

// round 13
// speedup vs baseline: 1.0536x; 1.0536x over previous
#include <cuda_runtime.h>
#include <cstdint>
#include <cstddef>

// ---------------- Problem constants ----------------
#define BTOT 16384   // b*n
#define FIN  2048
#define CIN  128
#define CFF  512
#define COUT 128
#define TPOS 16
#define BM   128
#define CH   64
#define NCHUNK 8
#define NTH  768     // G1 = 256 (8 warps), G2 = 512 (16 warps)

// ---------------- SMEM float offsets (XOR-swizzled, no padding) ----------------
// sA   [k=128][r=128]          @ 0       (16384 fl)
// sW1  [2][k=128][n=64]        @ 16384   (2 x 8192)
// sH   [2][k=64][r=128]        @ 32768   (2 x 8192)
// sW2  [k=64][o=128]           @ 49152   (8192)
#define SA_OFF   0
#define SW1_OFF  16384
#define SH_OFF   32768
#define SW2_OFF  49152
#define SMEM_FLOATS 57344
#define SMEM_BYTES (SMEM_FLOATS * 4)   // 229376 B
#define OS 132                          // epilogue sOut [o][r] stride (overlay @0)

// Named barriers: per-buffer produced/consumed pairs
#define BAR_P0 1   // sH[0] produced (G1 arrives 256, G2 syncs 512 -> count 768)
#define BAR_P1 2
#define BAR_C0 3   // sH[0] consumed (G2 arrives 512, G1 syncs 256 -> count 768)
#define BAR_C1 4
#define BAR_G1 5   // G1-internal (256)
#define BAR_G2 6   // G2-internal (512)

#define BARN(id, cnt)  asm volatile("bar.sync %0, %1;"   :: "r"(id), "r"(cnt) : "memory")
#define BARA(id, cnt)  asm volatile("bar.arrive %0, %1;" :: "r"(id), "r"(cnt) : "memory")

#define CP_ASYNC16(saddr, gptr) \
    asm volatile("cp.async.cg.shared.global [%0], [%1], 16;" :: "r"(saddr), "l"(gptr) : "memory")
#define CP_COMMIT() asm volatile("cp.async.commit_group;" ::: "memory")
#define CP_WAIT(n)  asm volatile("cp.async.wait_group %0;" :: "n"(n) : "memory")

// ---------------- Scratch (allocation-free rule) ----------------
__device__ float g_xT [2048ull * 16384];   // xT[f][row], f = c*16+t  (tf32-rounded)
__device__ float g_yT [2048ull * 16384];   // yT[f][row], f = o*16+t
__device__ float g_w1t[2048 * 512];        // w1t[(c*16+t)][o]        (tf32-rounded)
__device__ float g_w2t[8192 * 128];        // w2t[(k*16+t)][o]        (tf32-rounded)

__device__ __forceinline__ uint32_t smem_u32(const void* p) {
    uint32_t a;
    asm("{ .reg .u64 t; cvta.to.shared.u64 t, %1; cvt.u32.u64 %0, t; }" : "=r"(a) : "l"(p));
    return a;
}
__device__ __forceinline__ float tf32r(float x) {
    unsigned r;
    asm("cvt.rna.tf32.f32 %0, %1;" : "=r"(r) : "f"(x));
    return __uint_as_float(r);
}
// tanh-form GELU: 0.5x(1+tanh(sqrt(2/pi)(x+0.044715x^3))), hw tanh.approx.
// ~6 instr vs ~25 for erff; adds <=~4e-4 to norm rel_err (budget 1e-3).
__device__ __forceinline__ float gelu_fast(float x) {
    const float x2 = x * x;
    const float p  = x * fmaf(0.03567740814f, x2, 0.79788456080f);
    float th;
    asm("tanh.approx.f32 %0, %1;" : "=f"(th) : "f"(p));
    return 0.5f * x * (1.0f + th);
}
__device__ __forceinline__ void mma_tf32(float c[4], const unsigned a[4],
                                         unsigned b0, unsigned b1) {
    asm volatile(
        "mma.sync.aligned.m16n8k8.row.col.f32.tf32.tf32.f32 "
        "{%0,%1,%2,%3}, {%4,%5,%6,%7}, {%8,%9}, {%0,%1,%2,%3};\n"
        : "+f"(c[0]), "+f"(c[1]), "+f"(c[2]), "+f"(c[3])
        : "r"(a[0]), "r"(a[1]), "r"(a[2]), "r"(a[3]), "r"(b0), "r"(b1));
}

// ------------- Tiled transpose (+ optional tf32-RNA rounding): out[C][R] = in^T -------------
__global__ void transpose_kernel(float* __restrict__ out, const float* __restrict__ in,
                                 int R, int C, int doRound) {
    __shared__ float tile[32][33];
    const int bx = blockIdx.x * 32, by = blockIdx.y * 32;
    const int x = threadIdx.x & 31, y0 = threadIdx.x >> 5;
#pragma unroll
    for (int j = 0; j < 32; j += 8) {
        const int r = by + y0 + j, c = bx + x;
        if (r < R && c < C) {
            float v = in[(size_t)r * C + c];
            tile[y0 + j][x] = doRound ? tf32r(v) : v;
        }
    }
    __syncthreads();
#pragma unroll
    for (int j = 0; j < 32; j += 8) {
        const int c = bx + y0 + j, r = by + x;
        if (c < C && r < R) out[(size_t)c * R + r] = tile[x][y0 + j];
    }
}

// ------------------------------- Main warp-specialized kernel ----------------------------
__global__ void __launch_bounds__(NTH, 1)
jff_ws_kernel(const float* __restrict__ xT,
              const float* __restrict__ w1t,
              const float* __restrict__ w2t,
              float* __restrict__ yT)
{
    extern __shared__ float smem[];
    float* sA  = smem + SA_OFF;
    float* sW1 = smem + SW1_OFF;     // 2 buffers of 8192
    float* sH  = smem + SH_OFF;      // 2 buffers of 8192
    float* sW2 = smem + SW2_OFF;
    const uint32_t sb = smem_u32(smem);

    const int t   = blockIdx.x;      // t fastest -> L2 reuse of xT across t
    const int m0  = blockIdx.y * BM;
    const int tid = threadIdx.x;
    const int lane = tid & 31;
    const int g  = lane >> 2;        // 0..7
    const int qp = lane & 3;         // 0..3
    const int sw = qp << 3;          // XOR-swizzle term (thread-constant)

    if (tid < 256) {
        // ================= G1 (8 warps): GEMM1 + GELU producer =================
        const int w  = tid >> 5;         // 0..7
        const int wm = w & 3;            // 32-row slice
        const int wn = w >> 2;           // 0..1: 32-n slice

        // -- stage A tile via cp.async: 4096 16B chunks, 16 per thread --
#pragma unroll
        for (int i = 0; i < 16; i++) {
            const int q = tid + 256 * i;
            const int k = q >> 5, rq = q & 31;
            const uint32_t dst = sb + (uint32_t)(SA_OFF + k * 128 + ((4 * rq) ^ ((k & 3) << 3))) * 4;
            CP_ASYNC16(dst, &xT[(size_t)(k * TPOS + t) * BTOT + m0 + 4 * rq]);
        }
        CP_COMMIT();                                        // group: A
        // -- pre-stage W1 chunk 0 and 1 --
#pragma unroll
        for (int b = 0; b < 2; b++) {
#pragma unroll
            for (int i = 0; i < 8; i++) {
                const int q = tid + 256 * i;
                const int k = q >> 4, nq = q & 15;
                const uint32_t dst = sb + (uint32_t)(SW1_OFF + b * 8192 + k * 64 +
                                                     ((4 * nq) ^ ((k & 3) << 3))) * 4;
                CP_ASYNC16(dst, &w1t[(size_t)(k * TPOS + t) * CFF + b * CH + 4 * nq]);
            }
            CP_COMMIT();                                    // groups: W1[0], W1[1]
        }

        // thread-constant swizzled row indices
        int ra[2][2], rb[4];
#pragma unroll
        for (int mi = 0; mi < 2; mi++)
#pragma unroll
            for (int h = 0; h < 2; h++)
                ra[mi][h] = (wm * 32 + mi * 16 + h * 8 + g) ^ sw;
#pragma unroll
        for (int ni = 0; ni < 4; ni++)
            rb[ni] = (wn * 32 + ni * 8 + g) ^ sw;
        const int swHe = ((2 * qp) & 3) << 3;
        const int swHo = ((2 * qp + 1) & 3) << 3;

#pragma unroll 1
        for (int ch = 0; ch < NCHUNK; ch++) {
            if (ch < 7) { CP_WAIT(1); } else { CP_WAIT(0); }
            BARN(BAR_G1, 256);                              // W1[ch&1] (and A) visible group-wide
            const float* W1b = sW1 + (ch & 1) * 8192;

            // ---- GEMM1: c1[32r x 32n] = A[.,128] * W1^T ----
            float c1[2][4][4];
#pragma unroll
            for (int mi = 0; mi < 2; mi++)
#pragma unroll
                for (int ni = 0; ni < 4; ni++)
#pragma unroll
                    for (int j = 0; j < 4; j++) c1[mi][ni][j] = 0.0f;

#pragma unroll
            for (int ks = 0; ks < 16; ks++) {
                const int kA = ks * 8 + qp;
                unsigned a[2][4];
#pragma unroll
                for (int mi = 0; mi < 2; mi++) {
                    a[mi][0] = __float_as_uint(sA[kA * 128 + ra[mi][0]]);
                    a[mi][1] = __float_as_uint(sA[kA * 128 + ra[mi][1]]);
                    a[mi][2] = __float_as_uint(sA[(kA + 4) * 128 + ra[mi][0]]);
                    a[mi][3] = __float_as_uint(sA[(kA + 4) * 128 + ra[mi][1]]);
                }
#pragma unroll
                for (int ni = 0; ni < 4; ni++) {
                    const unsigned b0 = __float_as_uint(W1b[kA * 64 + rb[ni]]);
                    const unsigned b1 = __float_as_uint(W1b[(kA + 4) * 64 + rb[ni]]);
#pragma unroll
                    for (int mi = 0; mi < 2; mi++) mma_tf32(c1[mi][ni], a[mi], b0, b1);
                }
            }
            BARN(BAR_G1, 256);                              // all G1 done reading W1[ch&1]
            if (ch < 6) {                                   // restage this buffer for ch+2
#pragma unroll
                for (int i = 0; i < 8; i++) {
                    const int q = tid + 256 * i;
                    const int k = q >> 4, nq = q & 15;
                    const uint32_t dst = sb + (uint32_t)(SW1_OFF + (ch & 1) * 8192 + k * 64 +
                                                         ((4 * nq) ^ ((k & 3) << 3))) * 4;
                    CP_ASYNC16(dst, &w1t[(size_t)(k * TPOS + t) * CFF + (ch + 2) * CH + 4 * nq]);
                }
                CP_COMMIT();
            }

            if (ch >= 2) BARN(BAR_C0 + (ch & 1), NTH);      // G2 done with sH[ch&1] (chunk ch-2)

            // ---- fast GELU -> tf32 -> sH[ch&1][n][r] ----
            float* sHb = sH + (ch & 1) * 8192;
#pragma unroll
            for (int mi = 0; mi < 2; mi++) {
                const int r0 = wm * 32 + mi * 16 + g;
#pragma unroll
                for (int ni = 0; ni < 4; ni++) {
                    const int ne = wn * 32 + ni * 8 + 2 * qp;
                    sHb[ne * 128 + (r0 ^ swHe)]             = tf32r(gelu_fast(c1[mi][ni][0]));
                    sHb[(ne + 1) * 128 + (r0 ^ swHo)]       = tf32r(gelu_fast(c1[mi][ni][1]));
                    sHb[ne * 128 + ((r0 + 8) ^ swHe)]       = tf32r(gelu_fast(c1[mi][ni][2]));
                    sHb[(ne + 1) * 128 + ((r0 + 8) ^ swHo)] = tf32r(gelu_fast(c1[mi][ni][3]));
                }
            }
            BARA(BAR_P0 + (ch & 1), NTH);                   // publish sH[ch&1] (chunk ch)
        }
        // drain G2's final consumption arrivals (ch=6 on C0, ch=7 on C1)
        BARN(BAR_C0, NTH);
        BARN(BAR_C1, NTH);
    } else {
        // ================= G2 (16 warps): GEMM2 consumer =================
        const int u  = tid - 256;        // 0..511
        const int w  = u >> 5;           // 0..15
        const int wm = w & 3;            // 32-row slice
        const int wn = w >> 2;           // 0..3: 32-o slice

        // -- pre-stage W2 chunk 0: 2048 16B chunks, 4 per thread --
#pragma unroll
        for (int i = 0; i < 4; i++) {
            const int q = u + 512 * i;
            const int k = q >> 5, oq = q & 31;
            const uint32_t dst = sb + (uint32_t)(SW2_OFF + k * 128 + ((4 * oq) ^ ((k & 3) << 3))) * 4;
            CP_ASYNC16(dst, &w2t[(size_t)(k * TPOS + t) * COUT + 4 * oq]);
        }
        CP_COMMIT();

        int rh[2][2], ro[4];
#pragma unroll
        for (int mi = 0; mi < 2; mi++)
#pragma unroll
            for (int h = 0; h < 2; h++)
                rh[mi][h] = (wm * 32 + mi * 16 + h * 8 + g) ^ sw;
#pragma unroll
        for (int ni = 0; ni < 4; ni++)
            ro[ni] = (wn * 32 + ni * 8 + g) ^ sw;

        float acc[2][4][4];
#pragma unroll
        for (int mi = 0; mi < 2; mi++)
#pragma unroll
            for (int ni = 0; ni < 4; ni++)
#pragma unroll
                for (int j = 0; j < 4; j++) acc[mi][ni][j] = 0.0f;

#pragma unroll 1
        for (int ch = 0; ch < NCHUNK; ch++) {
            CP_WAIT(0);
            BARN(BAR_G2, 512);                              // W2(ch) visible group-wide
            BARN(BAR_P0 + (ch & 1), NTH);                   // sH[ch&1] produced (chunk ch)
            const float* sHb = sH + (ch & 1) * 8192;

            // ---- GEMM2: acc[32r x 32o] += H * W2^T ----
#pragma unroll
            for (int ks = 0; ks < 8; ks++) {
                const int kA = ks * 8 + qp;
                unsigned a[2][4];
#pragma unroll
                for (int mi = 0; mi < 2; mi++) {
                    a[mi][0] = __float_as_uint(sHb[kA * 128 + rh[mi][0]]);
                    a[mi][1] = __float_as_uint(sHb[kA * 128 + rh[mi][1]]);
                    a[mi][2] = __float_as_uint(sHb[(kA + 4) * 128 + rh[mi][0]]);
                    a[mi][3] = __float_as_uint(sHb[(kA + 4) * 128 + rh[mi][1]]);
                }
#pragma unroll
                for (int ni = 0; ni < 4; ni++) {
                    const unsigned b0 = __float_as_uint(sW2[kA * 128 + ro[ni]]);
                    const unsigned b1 = __float_as_uint(sW2[(kA + 4) * 128 + ro[ni]]);
#pragma unroll
                    for (int mi = 0; mi < 2; mi++) mma_tf32(acc[mi][ni], a[mi], b0, b1);
                }
            }
            BARN(BAR_G2, 512);                              // all G2 done reading W2(ch)
            if (ch < 7) {                                   // restage W2 for ch+1
#pragma unroll
                for (int i = 0; i < 4; i++) {
                    const int q = u + 512 * i;
                    const int k = q >> 5, oq = q & 31;
                    const uint32_t dst = sb + (uint32_t)(SW2_OFF + k * 128 +
                                                         ((4 * oq) ^ ((k & 3) << 3))) * 4;
                    CP_ASYNC16(dst, &w2t[(size_t)((ch + 1) * CH * TPOS + k * TPOS + t) * COUT + 4 * oq]);
                }
                CP_COMMIT();
            }
            BARA(BAR_C0 + (ch & 1), NTH);                   // sH[ch&1] consumed
        }

        // ---- G2 writes acc -> sO[o][r] (overlay @0; banks 8qp+g: conflict-free) ----
        // Safe: G1's last sA read precedes its P(ch7) arrive, which precedes our
        // P-sync at ch7 above.
        float* sO = smem;
#pragma unroll
        for (int mi = 0; mi < 2; mi++) {
            const int r0 = wm * 32 + mi * 16 + g;
#pragma unroll
            for (int ni = 0; ni < 4; ni++) {
                const int o0 = wn * 32 + ni * 8 + 2 * qp;
                sO[o0 * OS + r0]           = acc[mi][ni][0];
                sO[(o0 + 1) * OS + r0]     = acc[mi][ni][1];
                sO[o0 * OS + r0 + 8]       = acc[mi][ni][2];
                sO[(o0 + 1) * OS + r0 + 8] = acc[mi][ni][3];
            }
        }
    }

    __syncthreads();
    // ---- all 768 threads: coalesced yT stores (4096 float4 slots) ----
    {
        float* sO = smem;
        for (int idx = tid; idx < 4096; idx += NTH) {
            const int o = idx >> 5, rq = idx & 31;
            const float4 v = *(const float4*)&sO[o * OS + 4 * rq];
            *(float4*)&yT[(size_t)(o * TPOS + t) * BTOT + m0 + 4 * rq] = v;
        }
    }
}

extern "C" void kernel_launch(void* const* d_in, const int* in_sizes, int n_in,
                              void* d_out, int out_size)
{
    const float* x  = (const float*)d_in[0];   // [16384, 2048] fp32
    const float* w1 = (const float*)d_in[1];   // [512,128,16]  fp32
    const float* w2 = (const float*)d_in[2];   // [128,512,16]  fp32
    float* y = (float*)d_out;                  // [16384, 2048] fp32
    (void)in_sizes; (void)n_in; (void)out_size;

    float *xT, *yT, *w1t, *w2t;
    cudaGetSymbolAddress((void**)&xT,  g_xT);
    cudaGetSymbolAddress((void**)&yT,  g_yT);
    cudaGetSymbolAddress((void**)&w1t, g_w1t);
    cudaGetSymbolAddress((void**)&w2t, g_w2t);

    cudaFuncSetAttribute(jff_ws_kernel,
                         cudaFuncAttributeMaxDynamicSharedMemorySize, SMEM_BYTES);

    // 1) Layout transforms with tf32-RNA rounding folded in (raw-byte cp.async later)
    transpose_kernel<<<dim3(FIN / 32, BTOT / 32), 256>>>(xT, x, BTOT, FIN, 1);
    transpose_kernel<<<dim3(2048 / 32, 512 / 32), 256>>>(w1t, w1, CFF, CIN * TPOS, 1);
    transpose_kernel<<<dim3(8192 / 32, 128 / 32), 256>>>(w2t, w2, COUT, CFF * TPOS, 1);

    // 2) Warp-specialized fused locally-connected FFN (writes yT[f][row])
    dim3 grid(TPOS, BTOT / BM);
    jff_ws_kernel<<<grid, NTH, SMEM_BYTES>>>(xT, w1t, w2t, yT);

    // 3) yT -> y (no rounding)
    transpose_kernel<<<dim3(BTOT / 32, FIN / 32), 256>>>(y, yT, FIN, BTOT, 0);
}

// round 14
// speedup vs baseline: 1.0771x; 1.0223x over previous
#include <cuda_runtime.h>
#include <cstdint>
#include <cstddef>

// ---------------- Problem constants ----------------
#define BTOT 16384   // b*n
#define FIN  2048
#define CIN  128
#define CFF  512
#define COUT 128
#define TPOS 16
#define BM   128
#define CH   64
#define NCHUNK 8
#define NTH  768     // G1 = 256 (8 warps), G2 = 512 (16 warps)

// ---------------- SMEM float offsets ----------------
// sA   quad [kp=64][rq=64] f4   @ 0      (16384 fl)  image-packed (swizzle baked)
// sW1  2 x quad [kp=64][nq=32]  @ 16384  (2 x 8192)
// sH   2 x pair [kp=32][256 fl] @ 32768  (2 x 8192)
// sW2  quad [kp=32][nq=64]      @ 49152  (8192)
#define SA_OFF   0
#define SW1_OFF  16384
#define SH_OFF   32768
#define SW2_OFF  49152
#define SMEM_FLOATS 57344
#define SMEM_BYTES (SMEM_FLOATS * 4)   // 229376 B
#define OS 132                          // epilogue sOut [o][r] stride (overlay @0)

// Named barriers (identical protocol to R12/R13 — proven)
#define BAR_P0 1
#define BAR_P1 2
#define BAR_C0 3
#define BAR_C1 4
#define BAR_G1 5
#define BAR_G2 6

#define BARN(id, cnt)  asm volatile("bar.sync %0, %1;"   :: "r"(id), "r"(cnt) : "memory")
#define BARA(id, cnt)  asm volatile("bar.arrive %0, %1;" :: "r"(id), "r"(cnt) : "memory")

#define CP_ASYNC16(saddr, gptr) \
    asm volatile("cp.async.cg.shared.global [%0], [%1], 16;" :: "r"(saddr), "l"(gptr) : "memory")
#define CP_COMMIT() asm volatile("cp.async.commit_group;" ::: "memory")
#define CP_WAIT(n)  asm volatile("cp.async.wait_group %0;" :: "n"(n) : "memory")

// ---------------- Scratch (allocation-free rule) ----------------
// g_xQ : A quads,  per t: [kp=64][rqg=8192] float4, pre-swizzled (rq ^ 2*(kp&3))
// g_w1q: W1 quads, per (t,ch): [kp=64][nq=32] float4, pre-swizzled
// g_w2q: W2 quads, per (t,ch): [kp=32][nq=64] float4, pre-swizzled
__device__ float g_xQ [2048ull * 16384];
__device__ float g_yT [2048ull * 16384];   // yT[f][row], f = o*16+t
__device__ float g_w1q[2048 * 512];
__device__ float g_w2q[8192 * 128];

__device__ __forceinline__ uint32_t smem_u32(const void* p) {
    uint32_t a;
    asm("{ .reg .u64 t; cvta.to.shared.u64 t, %1; cvt.u32.u64 %0, t; }" : "=r"(a) : "l"(p));
    return a;
}
__device__ __forceinline__ float tf32r(float x) {
    unsigned r;
    asm("cvt.rna.tf32.f32 %0, %1;" : "=r"(r) : "f"(x));
    return __uint_as_float(r);
}
__device__ __forceinline__ float gelu_fast(float x) {
    const float x2 = x * x;
    const float p  = x * fmaf(0.03567740814f, x2, 0.79788456080f);
    float th;
    asm("tanh.approx.f32 %0, %1;" : "=f"(th) : "f"(p));
    return 0.5f * x * (1.0f + th);
}
__device__ __forceinline__ void mma_tf32(float c[4], unsigned a0, unsigned a1,
                                         unsigned a2, unsigned a3,
                                         unsigned b0, unsigned b1) {
    asm volatile(
        "mma.sync.aligned.m16n8k8.row.col.f32.tf32.tf32.f32 "
        "{%0,%1,%2,%3}, {%4,%5,%6,%7}, {%8,%9}, {%0,%1,%2,%3};\n"
        : "+f"(c[0]), "+f"(c[1]), "+f"(c[2]), "+f"(c[3])
        : "r"(a0), "r"(a1), "r"(a2), "r"(a3), "r"(b0), "r"(b1));
}

// ---------------- Pack x -> A-quad image (replaces x transpose) ----------------
// Quad (t, kp, rq) = ( A[c][r], A[c+4][r], A[c][r+8], A[c+4][r+8] ), tf32-rounded,
// stored at image position rq_img = rq ^ (2*(kp&3)).
__global__ void pack_x_kernel(float* __restrict__ out, const float* __restrict__ x) {
    extern __shared__ float st[];            // [128 f][stride 129]
    const int fb = blockIdx.x;               // 0..15  (f-tile of 128)
    const int rb = blockIdx.y;               // 0..127 (r-tile of 128)
    const int tid = threadIdx.x;             // 256

    // Phase 1: coalesced load + transpose to st[f_local][r_local], tf32-rounded
    const float4* x4 = (const float4*)x;
#pragma unroll
    for (int i = 0; i < 16; i++) {
        const int idx = tid + 256 * i;       // 4096 float4
        const int r_l = idx >> 5, fq = idx & 31;
        float4 v = x4[(size_t)(rb * 128 + r_l) * 512 + fb * 32 + fq];
        st[(4 * fq + 0) * 129 + r_l] = tf32r(v.x);
        st[(4 * fq + 1) * 129 + r_l] = tf32r(v.y);
        st[(4 * fq + 2) * 129 + r_l] = tf32r(v.z);
        st[(4 * fq + 3) * 129 + r_l] = tf32r(v.w);
    }
    __syncthreads();

    // Phase 2: emit quads. kp = fb*4 + kp_l; s = 2*kp_l.
    float4* out4 = (float4*)out;
#pragma unroll
    for (int t = 0; t < 16; t++) {
        const int kp_l   = tid >> 6;         // 0..3
        const int rq_img = tid & 63;
        const int rq     = rq_img ^ (2 * kp_l);
        const int r_l    = ((rq >> 3) << 4) + (rq & 7);
        const int f0     = kp_l * 16 + t;    // (c = cb+kp_l, t)
        const int f1     = f0 + 64;          // c + 4
        float4 v;
        v.x = st[f0 * 129 + r_l];
        v.y = st[f1 * 129 + r_l];
        v.z = st[f0 * 129 + r_l + 8];
        v.w = st[f1 * 129 + r_l + 8];
        out4[(size_t)(t * 64 + fb * 4 + kp_l) * 8192 + rb * 64 + rq_img] = v;
    }
}

// ---------------- Pack w1 -> quad image ----------------
// w1 layout (cff, cin, T): w1[(o*CIN + c)*TPOS + t]
__global__ void pack_w1_kernel(float* __restrict__ out, const float* __restrict__ w1) {
    const int tc = blockIdx.x;               // t*8 + ch
    const int t = tc >> 3, ch = tc & 7;
    float4* out4 = (float4*)out;
#pragma unroll
    for (int i = 0; i < 8; i++) {
        const int q = threadIdx.x + 256 * i; // 2048 quads
        const int kp = q >> 5, nq_img = q & 31;
        const int nq = nq_img ^ (2 * (kp & 3));
        const int c  = (kp >> 2) * 8 + (kp & 3);
        const int o  = ch * 64 + (nq >> 3) * 16 + (nq & 7);
        float4 v;
        v.x = tf32r(w1[((size_t)o * CIN + c) * TPOS + t]);
        v.y = tf32r(w1[((size_t)o * CIN + c + 4) * TPOS + t]);
        v.z = tf32r(w1[((size_t)(o + 8) * CIN + c) * TPOS + t]);
        v.w = tf32r(w1[((size_t)(o + 8) * CIN + c + 4) * TPOS + t]);
        out4[(size_t)tc * 2048 + q] = v;
    }
}

// ---------------- Pack w2 -> quad image ----------------
// w2 layout (cout, cff, T): w2[(o*CFF + k)*TPOS + t]
__global__ void pack_w2_kernel(float* __restrict__ out, const float* __restrict__ w2) {
    const int tc = blockIdx.x;               // t*8 + ch
    const int t = tc >> 3, ch = tc & 7;
    float4* out4 = (float4*)out;
#pragma unroll
    for (int i = 0; i < 8; i++) {
        const int q = threadIdx.x + 256 * i; // 2048 quads
        const int kp = q >> 6, nq_img = q & 63;
        const int nq = nq_img ^ (2 * (kp & 3));
        const int k  = ch * 64 + (kp >> 2) * 8 + (kp & 3);
        const int o  = (nq >> 3) * 16 + (nq & 7);
        float4 v;
        v.x = tf32r(w2[((size_t)o * CFF + k) * TPOS + t]);
        v.y = tf32r(w2[((size_t)o * CFF + k + 4) * TPOS + t]);
        v.z = tf32r(w2[((size_t)(o + 8) * CFF + k) * TPOS + t]);
        v.w = tf32r(w2[((size_t)(o + 8) * CFF + k + 4) * TPOS + t]);
        out4[(size_t)tc * 2048 + q] = v;
    }
}

// ------------- Tiled transpose (for y writeback): out[C][R] = in^T -------------
__global__ void transpose_kernel(float* __restrict__ out, const float* __restrict__ in,
                                 int R, int C) {
    __shared__ float tile[32][33];
    const int bx = blockIdx.x * 32, by = blockIdx.y * 32;
    const int x = threadIdx.x & 31, y0 = threadIdx.x >> 5;
#pragma unroll
    for (int j = 0; j < 32; j += 8) {
        const int r = by + y0 + j, c = bx + x;
        if (r < R && c < C) tile[y0 + j][x] = in[(size_t)r * C + c];
    }
    __syncthreads();
#pragma unroll
    for (int j = 0; j < 32; j += 8) {
        const int c = bx + y0 + j, r = by + x;
        if (c < C && r < R) out[(size_t)c * R + r] = tile[x][y0 + j];
    }
}

// ------------------------------- Main warp-specialized kernel ----------------------------
__global__ void __launch_bounds__(NTH, 1)
jff_ws_kernel(const float* __restrict__ xQ,
              const float* __restrict__ w1q,
              const float* __restrict__ w2q,
              float* __restrict__ yT)
{
    extern __shared__ float smem[];
    const float4* sA4  = (const float4*)(smem + SA_OFF);
    const float4* sW14 = (const float4*)(smem + SW1_OFF);
    float*        sHf  = smem + SH_OFF;
    const float2* sH2  = (const float2*)(smem + SH_OFF);
    const float4* sW24 = (const float4*)(smem + SW2_OFF);
    const uint32_t sb = smem_u32(smem);

    const float4* xQ4  = (const float4*)xQ;
    const float4* w1q4 = (const float4*)w1q;
    const float4* w2q4 = (const float4*)w2q;

    const int t   = blockIdx.x;      // t fastest
    const int m0  = blockIdx.y * BM;
    const int tid = threadIdx.x;
    const int lane = tid & 31;
    const int g  = lane >> 2;        // 0..7
    const int qp = lane & 3;         // 0..3

    if (tid < 256) {
        // ================= G1 (8 warps): GEMM1 + GELU producer =================
        const int w  = tid >> 5;
        const int wm = w & 3;
        const int wn = w >> 2;       // 0..1

        // -- stage A: pure linear copy of pre-packed image (4096 quads) --
        {
            const float4* src = xQ4 + (size_t)t * 64 * 8192 + (m0 >> 1);
#pragma unroll
            for (int i = 0; i < 16; i++) {
                const int q = tid + 256 * i;
                CP_ASYNC16(sb + SA_OFF * 4 + q * 16, src + (q >> 6) * 8192 + (q & 63));
            }
            CP_COMMIT();                                    // group: A
        }
        // -- pre-stage W1 chunk 0 and 1 (linear) --
#pragma unroll
        for (int b = 0; b < 2; b++) {
            const float4* src = w1q4 + (size_t)(t * 8 + b) * 2048;
#pragma unroll
            for (int i = 0; i < 8; i++) {
                const int q = tid + 256 * i;
                CP_ASYNC16(sb + SW1_OFF * 4 + b * 32768 + q * 16, src + q);
            }
            CP_COMMIT();                                    // groups: W1[0], W1[1]
        }

        // thread-constant quad indices
        const int ra0 = ((wm * 2 + 0) * 8 + g) ^ (2 * qp);
        const int ra1 = ((wm * 2 + 1) * 8 + g) ^ (2 * qp);
        const int nb0 = ((wn * 2 + 0) * 8 + g) ^ (2 * qp);
        const int nb1 = ((wn * 2 + 1) * 8 + g) ^ (2 * qp);
        // GELU store constants
        const int e0 = (2 * qp) & 3, e1 = (2 * qp + 1) & 3;
        const int sx0 = e0 << 2, sx1 = e1 << 2;
        const int half = qp >> 1;

#pragma unroll 1
        for (int ch = 0; ch < NCHUNK; ch++) {
            if (ch < 7) { CP_WAIT(1); } else { CP_WAIT(0); }
            BARN(BAR_G1, 256);
            const int w1b = (ch & 1) * 2048;                // float4 units

            // ---- GEMM1: c1[32r x 32n] ----
            float c1[2][4][4];
#pragma unroll
            for (int mi = 0; mi < 2; mi++)
#pragma unroll
                for (int ni = 0; ni < 4; ni++)
#pragma unroll
                    for (int j = 0; j < 4; j++) c1[mi][ni][j] = 0.0f;

#pragma unroll
            for (int ks = 0; ks < 16; ks++) {
                const int kb = ks * 4 + qp;
                const float4 qa0 = sA4[kb * 64 + ra0];
                const float4 qa1 = sA4[kb * 64 + ra1];
                const float4 qb0 = sW14[w1b + kb * 32 + nb0];
                const float4 qb1 = sW14[w1b + kb * 32 + nb1];
                // quad comp order: (k,r),(k+4,r),(k,r+8),(k+4,r+8) = (a0,a2,a1,a3)
#define A0(q) __float_as_uint((q).x)
#define A1(q) __float_as_uint((q).z)
#define A2(q) __float_as_uint((q).y)
#define A3(q) __float_as_uint((q).w)
                mma_tf32(c1[0][0], A0(qa0),A1(qa0),A2(qa0),A3(qa0),
                         __float_as_uint(qb0.x), __float_as_uint(qb0.y));
                mma_tf32(c1[1][0], A0(qa1),A1(qa1),A2(qa1),A3(qa1),
                         __float_as_uint(qb0.x), __float_as_uint(qb0.y));
                mma_tf32(c1[0][1], A0(qa0),A1(qa0),A2(qa0),A3(qa0),
                         __float_as_uint(qb0.z), __float_as_uint(qb0.w));
                mma_tf32(c1[1][1], A0(qa1),A1(qa1),A2(qa1),A3(qa1),
                         __float_as_uint(qb0.z), __float_as_uint(qb0.w));
                mma_tf32(c1[0][2], A0(qa0),A1(qa0),A2(qa0),A3(qa0),
                         __float_as_uint(qb1.x), __float_as_uint(qb1.y));
                mma_tf32(c1[1][2], A0(qa1),A1(qa1),A2(qa1),A3(qa1),
                         __float_as_uint(qb1.x), __float_as_uint(qb1.y));
                mma_tf32(c1[0][3], A0(qa0),A1(qa0),A2(qa0),A3(qa0),
                         __float_as_uint(qb1.z), __float_as_uint(qb1.w));
                mma_tf32(c1[1][3], A0(qa1),A1(qa1),A2(qa1),A3(qa1),
                         __float_as_uint(qb1.z), __float_as_uint(qb1.w));
            }
            BARN(BAR_G1, 256);
            if (ch < 6) {                                   // restage W1 buf for ch+2
                const float4* src = w1q4 + (size_t)(t * 8 + ch + 2) * 2048;
#pragma unroll
                for (int i = 0; i < 8; i++) {
                    const int q = tid + 256 * i;
                    CP_ASYNC16(sb + SW1_OFF * 4 + (ch & 1) * 32768 + q * 16, src + q);
                }
                CP_COMMIT();
            }

            if (ch >= 2) BARN(BAR_C0 + (ch & 1), NTH);

            // ---- GELU -> tf32 -> pair-H layout (conflict-free STS) ----
            float* hb = sHf + (ch & 1) * 8192;
#pragma unroll
            for (int mi = 0; mi < 2; mi++) {
                const int r0 = wm * 32 + mi * 16 + g;
#pragma unroll
                for (int ni = 0; ni < 4; ni++) {
                    const int kpb = (wn * 4 + ni) * 4;
                    hb[(kpb + e0) * 256 + 2 * (r0 ^ sx0) + half]       = tf32r(gelu_fast(c1[mi][ni][0]));
                    hb[(kpb + e1) * 256 + 2 * (r0 ^ sx1) + half]       = tf32r(gelu_fast(c1[mi][ni][1]));
                    hb[(kpb + e0) * 256 + 2 * ((r0 + 8) ^ sx0) + half] = tf32r(gelu_fast(c1[mi][ni][2]));
                    hb[(kpb + e1) * 256 + 2 * ((r0 + 8) ^ sx1) + half] = tf32r(gelu_fast(c1[mi][ni][3]));
                }
            }
            BARA(BAR_P0 + (ch & 1), NTH);
        }
        BARN(BAR_C0, NTH);
        BARN(BAR_C1, NTH);
    } else {
        // ================= G2 (16 warps): GEMM2 consumer =================
        const int u  = tid - 256;
        const int w  = u >> 5;           // 0..15
        const int wm = w & 3;
        const int wn = w >> 2;           // 0..3

        // -- pre-stage W2 chunk 0 (linear) --
        {
            const float4* src = w2q4 + (size_t)(t * 8) * 2048;
#pragma unroll
            for (int i = 0; i < 4; i++) {
                const int q = u + 512 * i;
                CP_ASYNC16(sb + SW2_OFF * 4 + q * 16, src + q);
            }
            CP_COMMIT();
        }

        const int rh0 = wm * 32 + g;               // mi=0 row (mi=1: +16)
        const int no0 = ((wn * 2 + 0) * 8 + g) ^ (2 * qp);
        const int no1 = ((wn * 2 + 1) * 8 + g) ^ (2 * qp);
        const int hsw = qp << 2;

        float acc[2][4][4];
#pragma unroll
        for (int mi = 0; mi < 2; mi++)
#pragma unroll
            for (int ni = 0; ni < 4; ni++)
#pragma unroll
                for (int j = 0; j < 4; j++) acc[mi][ni][j] = 0.0f;

#pragma unroll 1
        for (int ch = 0; ch < NCHUNK; ch++) {
            CP_WAIT(0);
            BARN(BAR_G2, 512);
            BARN(BAR_P0 + (ch & 1), NTH);
            const int h2b = (ch & 1) * 4096;               // float2 units

            // ---- GEMM2: acc[32r x 32o] += H * W2^T ----
#pragma unroll
            for (int ks = 0; ks < 8; ks++) {
                const int kb = ks * 4 + qp;
                const float2 h00 = sH2[h2b + kb * 128 + (rh0 ^ hsw)];
                const float2 h01 = sH2[h2b + kb * 128 + ((rh0 + 8) ^ hsw)];
                const float2 h10 = sH2[h2b + kb * 128 + ((rh0 + 16) ^ hsw)];
                const float2 h11 = sH2[h2b + kb * 128 + ((rh0 + 24) ^ hsw)];
                const float4 qb0 = sW24[kb * 64 + no0];
                const float4 qb1 = sW24[kb * 64 + no1];
                // pair comps: (.x = H[k][r], .y = H[k+4][r]) -> a0=.x, a2=.y
                mma_tf32(acc[0][0], __float_as_uint(h00.x), __float_as_uint(h01.x),
                                    __float_as_uint(h00.y), __float_as_uint(h01.y),
                         __float_as_uint(qb0.x), __float_as_uint(qb0.y));
                mma_tf32(acc[1][0], __float_as_uint(h10.x), __float_as_uint(h11.x),
                                    __float_as_uint(h10.y), __float_as_uint(h11.y),
                         __float_as_uint(qb0.x), __float_as_uint(qb0.y));
                mma_tf32(acc[0][1], __float_as_uint(h00.x), __float_as_uint(h01.x),
                                    __float_as_uint(h00.y), __float_as_uint(h01.y),
                         __float_as_uint(qb0.z), __float_as_uint(qb0.w));
                mma_tf32(acc[1][1], __float_as_uint(h10.x), __float_as_uint(h11.x),
                                    __float_as_uint(h10.y), __float_as_uint(h11.y),
                         __float_as_uint(qb0.z), __float_as_uint(qb0.w));
                mma_tf32(acc[0][2], __float_as_uint(h00.x), __float_as_uint(h01.x),
                                    __float_as_uint(h00.y), __float_as_uint(h01.y),
                         __float_as_uint(qb1.x), __float_as_uint(qb1.y));
                mma_tf32(acc[1][2], __float_as_uint(h10.x), __float_as_uint(h11.x),
                                    __float_as_uint(h10.y), __float_as_uint(h11.y),
                         __float_as_uint(qb1.x), __float_as_uint(qb1.y));
                mma_tf32(acc[0][3], __float_as_uint(h00.x), __float_as_uint(h01.x),
                                    __float_as_uint(h00.y), __float_as_uint(h01.y),
                         __float_as_uint(qb1.z), __float_as_uint(qb1.w));
                mma_tf32(acc[1][3], __float_as_uint(h10.x), __float_as_uint(h11.x),
                                    __float_as_uint(h10.y), __float_as_uint(h11.y),
                         __float_as_uint(qb1.z), __float_as_uint(qb1.w));
            }
            BARN(BAR_G2, 512);
            if (ch < 7) {                                   // restage W2 for ch+1
                const float4* src = w2q4 + (size_t)(t * 8 + ch + 1) * 2048;
#pragma unroll
                for (int i = 0; i < 4; i++) {
                    const int q = u + 512 * i;
                    CP_ASYNC16(sb + SW2_OFF * 4 + q * 16, src + q);
                }
                CP_COMMIT();
            }
            BARA(BAR_C0 + (ch & 1), NTH);
        }

        // ---- acc -> sO[o][r] (overlay @0; banks 8qp+g: conflict-free) ----
        float* sO = smem;
#pragma unroll
        for (int mi = 0; mi < 2; mi++) {
            const int r0 = wm * 32 + mi * 16 + g;
#pragma unroll
            for (int ni = 0; ni < 4; ni++) {
                const int o0 = wn * 32 + ni * 8 + 2 * qp;
                sO[o0 * OS + r0]           = acc[mi][ni][0];
                sO[(o0 + 1) * OS + r0]     = acc[mi][ni][1];
                sO[o0 * OS + r0 + 8]       = acc[mi][ni][2];
                sO[(o0 + 1) * OS + r0 + 8] = acc[mi][ni][3];
            }
        }
    }

    __syncthreads();
    // ---- all threads: coalesced yT stores ----
    {
        float* sO = smem;
        for (int idx = tid; idx < 4096; idx += NTH) {
            const int o = idx >> 5, rq = idx & 31;
            const float4 v = *(const float4*)&sO[o * OS + 4 * rq];
            *(float4*)&yT[(size_t)(o * TPOS + t) * BTOT + m0 + 4 * rq] = v;
        }
    }
}

extern "C" void kernel_launch(void* const* d_in, const int* in_sizes, int n_in,
                              void* d_out, int out_size)
{
    const float* x  = (const float*)d_in[0];   // [16384, 2048] fp32
    const float* w1 = (const float*)d_in[1];   // [512,128,16]  fp32
    const float* w2 = (const float*)d_in[2];   // [128,512,16]  fp32
    float* y = (float*)d_out;                  // [16384, 2048] fp32
    (void)in_sizes; (void)n_in; (void)out_size;

    float *xQ, *yT, *w1q, *w2q;
    cudaGetSymbolAddress((void**)&xQ,  g_xQ);
    cudaGetSymbolAddress((void**)&yT,  g_yT);
    cudaGetSymbolAddress((void**)&w1q, g_w1q);
    cudaGetSymbolAddress((void**)&w2q, g_w2q);

    cudaFuncSetAttribute(jff_ws_kernel,
                         cudaFuncAttributeMaxDynamicSharedMemorySize, SMEM_BYTES);
    cudaFuncSetAttribute(pack_x_kernel,
                         cudaFuncAttributeMaxDynamicSharedMemorySize, 128 * 129 * 4);

    // 1) Pack operands into fragment-quad images (tf32-RNA baked in)
    pack_x_kernel<<<dim3(16, 128), 256, 128 * 129 * 4>>>(xQ, x);
    pack_w1_kernel<<<128, 256>>>(w1q, w1);
    pack_w2_kernel<<<128, 256>>>(w2q, w2);

    // 2) Warp-specialized fused locally-connected FFN (writes yT[f][row])
    dim3 grid(TPOS, BTOT / BM);
    jff_ws_kernel<<<grid, NTH, SMEM_BYTES>>>(xQ, w1q, w2q, yT);

    // 3) yT -> y
    transpose_kernel<<<dim3(BTOT / 32, FIN / 32), 256>>>(y, yT, FIN, BTOT);
}